// round 4
// baseline (speedup 1.0000x reference)
#include <cuda_runtime.h>
#include <cstdint>

#define WPB 8          // warps per block
#define EPW 4          // elements per warp
#define NTHREADS 256
#define D 64
#define NS 8

typedef unsigned long long ull;

__device__ __forceinline__ ull pack2(float x, float y){
    ull r;
    asm("mov.b64 %0, {%1, %2};" : "=l"(r)
        : "r"(__float_as_uint(x)), "r"(__float_as_uint(y)));
    return r;
}
__device__ __forceinline__ void unpack2(ull p, float &x, float &y){
    unsigned int lo, hi;
    asm("mov.b64 {%0, %1}, %2;" : "=r"(lo), "=r"(hi) : "l"(p));
    x = __uint_as_float(lo); y = __uint_as_float(hi);
}
// packed fp32x2 ops (Blackwell)
__device__ __forceinline__ void ffma2(ull &acc, ull a, ull b){
    asm("fma.rn.f32x2 %0, %1, %2, %3;" : "=l"(acc) : "l"(a), "l"(b), "l"(acc));
}
__device__ __forceinline__ ull add2(ull a, ull b){
    ull r; asm("add.rn.f32x2 %0, %1, %2;" : "=l"(r) : "l"(a), "l"(b));
    return r;
}

// softmax over 8-lane group (lanes e*8 .. e*8+7), one value per lane
__device__ __forceinline__ float gsoftmax8(float x){
    float m = x;
    m = fmaxf(m, __shfl_xor_sync(0xffffffffu, m, 1));
    m = fmaxf(m, __shfl_xor_sync(0xffffffffu, m, 2));
    m = fmaxf(m, __shfl_xor_sync(0xffffffffu, m, 4));
    float e = __expf(x - m);
    float sm = e;
    sm += __shfl_xor_sync(0xffffffffu, sm, 1);
    sm += __shfl_xor_sync(0xffffffffu, sm, 2);
    sm += __shfl_xor_sync(0xffffffffu, sm, 4);
    return e / sm;
}

// replicated 8-way softmax (for attention scores already held by every lane)
__device__ __forceinline__ void softmax8(float* w){
    float m = w[0];
    #pragma unroll
    for (int s = 1; s < NS; s++) m = fmaxf(m, w[s]);
    float sum = 0.f;
    #pragma unroll
    for (int s = 0; s < NS; s++){ w[s] = __expf(w[s] - m); sum += w[s]; }
    float inv = 1.f / sum;
    #pragma unroll
    for (int s = 0; s < NS; s++) w[s] *= inv;
}

// matvec: W from gmem (L1-resident), x broadcast from registers via shfl.b64.
// lane l holds x dims (2l, 2l+1) in xpk[e]; output pair per lane, relu applied.
__device__ __forceinline__ void matvec(const ull* __restrict__ Wg,
                                       const ull* __restrict__ bg,
                                       const ull* xpk, ull* h, int lane){
    ull bias = bg[lane];
    ull acc[EPW];
    #pragma unroll
    for (int e = 0; e < EPW; e++) acc[e] = bias;
    #pragma unroll 8
    for (int dd = 0; dd < D/2; dd++){
        ull w0 = Wg[(2*dd)  * 32 + lane];   // (W[2dd][2l],   W[2dd][2l+1])
        ull w1 = Wg[(2*dd+1)* 32 + lane];
        #pragma unroll
        for (int e = 0; e < EPW; e++){
            ull xp = __shfl_sync(0xffffffffu, xpk[e], dd);
            float x0, x1; unpack2(xp, x0, x1);
            ffma2(acc[e], w0, pack2(x0, x0));
            ffma2(acc[e], w1, pack2(x1, x1));
        }
    }
    #pragma unroll
    for (int e = 0; e < EPW; e++){
        float a, b; unpack2(acc[e], a, b);
        h[e] = pack2(fmaxf(a, 0.f), fmaxf(b, 0.f));
    }
}

__global__ void __launch_bounds__(NTHREADS, 5)
sestkgcn_kernel(
    const int* __restrict__ u, const int* __restrict__ v,
    const float* __restrict__ usr_feat, const float* __restrict__ item_feat,
    const float* __restrict__ rel_feat,
    const int* __restrict__ neigh_uu, const float* __restrict__ uu_st,
    const int* __restrict__ neigh_ui, const float* __restrict__ ui_rat,
    const float* __restrict__ ui_vot, const float* __restrict__ ui_tim,
    const int* __restrict__ neigh_iu, const float* __restrict__ iu_rat,
    const float* __restrict__ iu_vot, const float* __restrict__ iu_tim,
    const int* __restrict__ neigh_ii, const int* __restrict__ neigh_ir,
    const float* __restrict__ Wu, const float* __restrict__ bu,
    const float* __restrict__ Wv, const float* __restrict__ bv,
    float* __restrict__ out, int batch)
{
    const int lane = threadIdx.x & 31;
    const int warp = threadIdx.x >> 5;
    const int base = (blockIdx.x * WPB + warp) * EPW;

    const float2* usr2  = (const float2*)usr_feat;   // vector base = id*32 + lane
    const float2* item2 = (const float2*)item_feat;
    const float2* rel2  = (const float2*)rel_feat;

    // ---------- lane-parallel weights & indices: lane = (e = lane>>3, s = lane&7) ----------
    const int eg = lane >> 3, sg = lane & 7;
    int bb = base + eg; if (bb >= batch) bb = batch - 1;
    const int myu = u[bb];
    const int myv = v[bb];

    float w_uu = uu_st[myu*NS + sg];
    int   i_uu = neigh_uu[myu*NS + sg];
    float w_ui = ui_rat[myu*NS + sg] * ui_vot[myu*NS + sg] * ui_tim[myu*NS + sg];
    int   i_ui = neigh_ui[myu*NS + sg];
    float w_iu = iu_rat[myv*NS + sg] * iu_vot[myv*NS + sg] * iu_tim[myv*NS + sg];
    int   i_iu = neigh_iu[myv*NS + sg];
    int   i_ii = neigh_ii[myv*NS + sg];
    int   i_ir = neigh_ir[myv*NS + sg];

    w_uu = gsoftmax8(w_uu);
    w_ui = gsoftmax8(w_ui);
    w_iu = gsoftmax8(w_iu);

    const ull p_uu = pack2(w_uu, __int_as_float(i_uu));
    const ull p_ui = pack2(w_ui, __int_as_float(i_ui));
    const ull p_iu = pack2(w_iu, __int_as_float(i_iu));
    const ull p_ii = pack2(__int_as_float(i_ii), __int_as_float(i_ir));

    // ---------- u_emb gathers (needed for KG attention too) ----------
    ull uepk[EPW];
    #pragma unroll
    for (int e = 0; e < EPW; e++){
        int ue_id = __shfl_sync(0xffffffffu, myu, e << 3);
        float2 t = usr2[ue_id*32 + lane];
        uepk[e] = pack2(t.x, t.y);
    }

    ull xpk[EPW];   // aggregated vector (pair per lane), reused user->item
    ull uh[EPW], vh[EPW];

    // =============== user side: gather + aggregate ===============
    #pragma unroll
    for (int e = 0; e < EPW; e++){
        float ax, ay; unpack2(uepk[e], ax, ay);

        // social neighbors
        {
            float w[NS]; float2 f[NS];
            #pragma unroll
            for (int s = 0; s < NS; s++){
                ull t = __shfl_sync(0xffffffffu, p_uu, (e << 3) + s);
                float wf, idf; unpack2(t, wf, idf);
                w[s] = wf;
                f[s] = usr2[__float_as_int(idf)*32 + lane];
            }
            #pragma unroll
            for (int s = 0; s < NS; s++){
                ax = fmaf(w[s], f[s].x, ax);
                ay = fmaf(w[s], f[s].y, ay);
            }
        }
        // interacted items
        {
            float w[NS]; float2 f[NS];
            #pragma unroll
            for (int s = 0; s < NS; s++){
                ull t = __shfl_sync(0xffffffffu, p_ui, (e << 3) + s);
                float wf, idf; unpack2(t, wf, idf);
                w[s] = wf;
                f[s] = item2[__float_as_int(idf)*32 + lane];
            }
            #pragma unroll
            for (int s = 0; s < NS; s++){
                ax = fmaf(w[s], f[s].x, ax);
                ay = fmaf(w[s], f[s].y, ay);
            }
        }
        xpk[e] = pack2(ax, ay);
    }

    // =============== user matvec: relu(x @ Wu + bu) ===============
    matvec((const ull*)Wu, (const ull*)bu, xpk, uh, lane);

    // =============== item side: gather + aggregate ===============
    #pragma unroll
    for (int e = 0; e < EPW; e++){
        int ve_id = __shfl_sync(0xffffffffu, myv, e << 3);
        float2 vt = item2[ve_id*32 + lane];
        float ax = vt.x, ay = vt.y;

        // interacting users
        {
            float w[NS]; float2 f[NS];
            #pragma unroll
            for (int s = 0; s < NS; s++){
                ull t = __shfl_sync(0xffffffffu, p_iu, (e << 3) + s);
                float wf, idf; unpack2(t, wf, idf);
                w[s] = wf;
                f[s] = usr2[__float_as_int(idf)*32 + lane];
            }
            #pragma unroll
            for (int s = 0; s < NS; s++){
                ax = fmaf(w[s], f[s].x, ax);
                ay = fmaf(w[s], f[s].y, ay);
            }
        }
        // KG neighbors with user-relation attention
        {
            float ux, uy; unpack2(uepk[e], ux, uy);
            int iidx[NS]; float ps[NS];
            #pragma unroll
            for (int s = 0; s < NS; s++){
                ull t = __shfl_sync(0xffffffffu, p_ii, (e << 3) + s);
                float af, bf; unpack2(t, af, bf);
                iidx[s] = __float_as_int(af);
                float2 rf = rel2[__float_as_int(bf)*32 + lane];
                ps[s] = fmaf(ux, rf.x, uy * rf.y);
            }
            // packed butterfly: reduce 8 dots across the warp simultaneously
            ull q0 = pack2(ps[0], ps[1]), q1 = pack2(ps[2], ps[3]);
            ull q2 = pack2(ps[4], ps[5]), q3 = pack2(ps[6], ps[7]);
            #pragma unroll
            for (int o = 16; o; o >>= 1){
                q0 = add2(q0, __shfl_xor_sync(0xffffffffu, q0, o));
                q1 = add2(q1, __shfl_xor_sync(0xffffffffu, q1, o));
                q2 = add2(q2, __shfl_xor_sync(0xffffffffu, q2, o));
                q3 = add2(q3, __shfl_xor_sync(0xffffffffu, q3, o));
            }
            float att[NS];
            unpack2(q0, att[0], att[1]); unpack2(q1, att[2], att[3]);
            unpack2(q2, att[4], att[5]); unpack2(q3, att[6], att[7]);
            softmax8(att);
            float2 f[NS];
            #pragma unroll
            for (int s = 0; s < NS; s++) f[s] = item2[iidx[s]*32 + lane];
            #pragma unroll
            for (int s = 0; s < NS; s++){
                ax = fmaf(att[s], f[s].x, ax);
                ay = fmaf(att[s], f[s].y, ay);
            }
        }
        xpk[e] = pack2(ax, ay);
    }

    // =============== item matvec: relu(x @ Wv + bv) ===============
    matvec((const ull*)Wv, (const ull*)bv, xpk, vh, lane);

    // =============== score: sigmoid(dot(user_h, item_h)) * 5 ===============
    float pe[EPW];
    #pragma unroll
    for (int e = 0; e < EPW; e++){
        float a0, a1, b0, b1;
        unpack2(uh[e], a0, a1);
        unpack2(vh[e], b0, b1);
        pe[e] = fmaf(a0, b0, a1 * b1);
    }
    ull s01 = pack2(pe[0], pe[1]), s23 = pack2(pe[2], pe[3]);
    #pragma unroll
    for (int o = 16; o; o >>= 1){
        s01 = add2(s01, __shfl_xor_sync(0xffffffffu, s01, o));
        s23 = add2(s23, __shfl_xor_sync(0xffffffffu, s23, o));
    }
    if (lane == 0){
        float r[EPW];
        unpack2(s01, r[0], r[1]);
        unpack2(s23, r[2], r[3]);
        #pragma unroll
        for (int e = 0; e < EPW; e++)
            if (base + e < batch)
                out[base + e] = 5.f / (1.f + __expf(-r[e]));
    }
}

extern "C" void kernel_launch(void* const* d_in, const int* in_sizes, int n_in,
                              void* d_out, int out_size)
{
    (void)n_in; (void)out_size;
    const int batch = in_sizes[0];
    const int blocks = (batch + WPB*EPW - 1) / (WPB*EPW);
    sestkgcn_kernel<<<blocks, NTHREADS>>>(
        (const int*)d_in[0],  (const int*)d_in[1],
        (const float*)d_in[2], (const float*)d_in[3], (const float*)d_in[4],
        (const int*)d_in[5],  (const float*)d_in[6],
        (const int*)d_in[7],  (const float*)d_in[8],  (const float*)d_in[9],  (const float*)d_in[10],
        (const int*)d_in[11], (const float*)d_in[12], (const float*)d_in[13], (const float*)d_in[14],
        (const int*)d_in[15], (const int*)d_in[16],
        (const float*)d_in[17], (const float*)d_in[18],
        (const float*)d_in[19], (const float*)d_in[20],
        (float*)d_out, batch);
}